// round 16
// baseline (speedup 1.0000x reference)
#include <cuda_runtime.h>
#include <cuda_bf16.h>
#include <mma.h>
#include <math.h>
#include <cstdint>

using namespace nvcuda;

#define NB 8
#define NT 512
#define NS 128
#define NC 512
#define RR 19
#define NS1 129
#define NT1 513
#define NT1P 520
#define MROWS (NB*NT*RR)
#define NEGF (-1e20f)

// ---------------- device scratch (allocation-free module globals) -----------
__device__ float g_lm_max[NB*NS1];
__device__ float g_lm_lse[NB*NS1];
__device__ float g_lm_p[(size_t)NB*NS1*NC];
__device__ float g_am_max[NB*NT];
__device__ float g_am_p[(size_t)NB*NT*NC];
__device__ float g_px[(size_t)NB*NS*NT1];
__device__ float g_py[(size_t)NB*NS1*NT];
__device__ float g_alpha[(size_t)NB*NS1*NT1P];
__device__ float g_beta[(size_t)NB*NS1*NT1P];
__device__ float g_total[NB];
__device__ float g_total2[NB];
__device__ float g_pxg[(size_t)NB*NS*NT1];
__device__ float g_pyg[(size_t)NB*NS1*NT];
__device__ int   g_sb[NB*NT];
__device__ __nv_bfloat16 g_A[(size_t)MROWS*NC];
__device__ __nv_bfloat16 g_W[NC*NC];
__device__ float g_pmax[(size_t)MROWS*4];
__device__ float g_psum[(size_t)MROWS*4];
__device__ float g_pxv[MROWS];
__device__ float g_pyv[MROWS];
__device__ float g_pxf[(size_t)NB*NS*NT1];
__device__ float g_pyf[(size_t)NB*NS1*NT];

// ---------------- helpers ----------------
__device__ __forceinline__ float warpmax(float v){
  #pragma unroll
  for(int o=16;o>0;o>>=1) v=fmaxf(v,__shfl_xor_sync(0xffffffffu,v,o));
  return v;
}
__device__ __forceinline__ float warpsum(float v){
  #pragma unroll
  for(int o=16;o>0;o>>=1) v+=__shfl_xor_sync(0xffffffffu,v,o);
  return v;
}
// fast logaddexp via MUFU ex2/lg2 (err ~1e-7 abs)
__device__ __forceinline__ float lae2(float a,float b){
  float mx=fmaxf(a,b), mn=fminf(a,b);
  float d = (mn-mx)*1.4426950408889634f;
  float e; asm("ex2.approx.f32 %0, %1;" : "=f"(e) : "f"(d));
  float l; asm("lg2.approx.f32 %0, %1;" : "=f"(l) : "f"(1.0f+e));
  return mx + l*0.6931471805599453f;
}
__device__ __forceinline__ float tanh_ap(float x){
  float r; asm("tanh.approx.f32 %0, %1;" : "=f"(r) : "f"(x)); return r;
}
__device__ __forceinline__ void cp16(uint32_t dst, const void* src){
  asm volatile("cp.async.cg.shared.global [%0], [%1], 16;" :: "r"(dst), "l"(src));
}

// ---------------- merged row stats (lm rows then am rows) -------------------
__global__ void k_stats(const float* __restrict__ lm, const float* __restrict__ am){
  int row = blockIdx.x*8 + (threadIdx.x>>5);
  int lane = threadIdx.x & 31;
  if(row < NB*NS1){
    const float* L = lm + (size_t)row*NC;
    float v[16]; float mx = -3.4e38f;
    #pragma unroll
    for(int j=0;j<16;j++){ v[j]=L[lane+32*j]; mx=fmaxf(mx,v[j]); }
    mx = warpmax(mx);
    float s = 0.f;
    #pragma unroll
    for(int j=0;j<16;j++){ float e=expf(v[j]-mx); s+=e; g_lm_p[(size_t)row*NC+lane+32*j]=e; }
    s = warpsum(s);
    if(lane==0){ g_lm_max[row]=mx; g_lm_lse[row]=mx+logf(s); }
  } else {
    int r = row - NB*NS1;
    if(r >= NB*NT) return;
    const float* A = am + (size_t)r*NC;
    float v[16]; float mx = -3.4e38f;
    #pragma unroll
    for(int j=0;j<16;j++){ v[j]=A[lane+32*j]; mx=fmaxf(mx,v[j]); }
    mx = warpmax(mx);
    #pragma unroll
    for(int j=0;j<16;j++) g_am_p[(size_t)r*NC + lane+32*j] = expf(v[j]-mx);
    if(lane==0) g_am_max[r]=mx;
  }
}

// ---- normalizers (64x64 tile, 4x4 reg blocking) + fused px/py epilogue -----
__global__ void __launch_bounds__(256) k_norm(const float* __restrict__ am,
                                              const float* __restrict__ lm,
                                              const int* __restrict__ tg){
  int b = blockIdx.z, s0 = blockIdx.y*64, t0 = blockIdx.x*64;
  __shared__ float Ls[64][17], Am[64][17];
  int tid = threadIdx.x;
  int ty = tid>>4, tx = tid&15;
  float acc[4][4];
  #pragma unroll
  for(int i=0;i<4;i++)
    #pragma unroll
    for(int j=0;j<4;j++) acc[i][j]=0.f;

  int lr = tid>>2, lq = (tid&3)*4;
  for(int c0=0;c0<NC;c0+=16){
    {
      int s = s0 + lr;
      float4 v = (s<NS1) ? *(const float4*)&g_lm_p[((size_t)b*NS1+s)*NC + c0 + lq]
                         : make_float4(0.f,0.f,0.f,0.f);
      Ls[lr][lq]=v.x; Ls[lr][lq+1]=v.y; Ls[lr][lq+2]=v.z; Ls[lr][lq+3]=v.w;
    }
    {
      float4 v = *(const float4*)&g_am_p[((size_t)b*NT + t0 + lr)*NC + c0 + lq];
      Am[lr][lq]=v.x; Am[lr][lq+1]=v.y; Am[lr][lq+2]=v.z; Am[lr][lq+3]=v.w;
    }
    __syncthreads();
    #pragma unroll
    for(int c=0;c<16;c++){
      float a0=Ls[ty*4+0][c], a1=Ls[ty*4+1][c], a2=Ls[ty*4+2][c], a3=Ls[ty*4+3][c];
      float e0=Am[tx*4+0][c], e1=Am[tx*4+1][c], e2=Am[tx*4+2][c], e3=Am[tx*4+3][c];
      acc[0][0]+=a0*e0; acc[0][1]+=a0*e1; acc[0][2]+=a0*e2; acc[0][3]+=a0*e3;
      acc[1][0]+=a1*e0; acc[1][1]+=a1*e1; acc[1][2]+=a1*e2; acc[1][3]+=a1*e3;
      acc[2][0]+=a2*e0; acc[2][1]+=a2*e1; acc[2][2]+=a2*e2; acc[2][3]+=a2*e3;
      acc[3][0]+=a3*e0; acc[3][1]+=a3*e1; acc[3][2]+=a3*e2; acc[3][3]+=a3*e3;
    }
    __syncthreads();
  }
  #pragma unroll
  for(int i=0;i<4;i++){
    int s = s0 + ty*4 + i;
    if(s >= NS1) continue;
    float lmx = g_lm_max[b*NS1+s];
    float lse = g_lm_lse[b*NS1+s];
    float lm0 = lm[((size_t)b*NS1+s)*NC];
    int sym = (s<NS) ? tg[b*NS+s] : 0;
    float lms = (s<NS) ? lm[((size_t)b*NS1+s)*NC + sym] : 0.f;
    #pragma unroll
    for(int j=0;j<4;j++){
      int t = t0 + tx*4 + j;
      float nrm = logf(acc[i][j]) + lmx + g_am_max[b*NT+t];
      float am0 = am[((size_t)b*NT+t)*NC];
      g_py[((size_t)b*NS1+s)*NT+t] = 0.75f*(am0+lm0-nrm) + 0.25f*(lm0-lse);
      if(s<NS){
        float ams = am[((size_t)b*NT+t)*NC + sym];
        g_px[((size_t)b*NS+s)*NT1+t] = 0.75f*(ams+lms-nrm) + 0.25f*(lms-lse);
      }
    }
  }
}

// ---------------- W conversion + px t=NT sentinel init ----------------------
__global__ void k_convW(const float* __restrict__ w){
  int idx = blockIdx.x*blockDim.x + threadIdx.x;
  if(idx < NC*NC) g_W[idx] = __float2bfloat16(w[idx]);
  if(idx < NB*NS) g_px[(size_t)idx*NT1 + NT] = NEGF;
}

// ------ lattice DP: coarse wavefront, 65 threads, R=2 rows x W=8 cols -------
// Inline operand loads (no register double-buffer => no spills).
__global__ void __launch_bounds__(65) k_dp(int which){
  int b = blockIdx.x;
  int dir = blockIdx.y;
  const float* PX = (which ? g_pxf : g_px) + (size_t)b*NS*NT1;
  const float* PY = (which ? g_pyf : g_py) + (size_t)b*NS1*NT;
  float* TOT = which ? g_total2 : g_total;
  int i = threadIdx.x;
  __shared__ float prevbuf[2][65][9];   // padded stride 9: conflict-free

  if(dir==0){
    int s0 = 2*i, s1 = 2*i+1;
    bool hasB = (s1 <= NS);
    float* AL = g_alpha + (size_t)b*NS1*NT1P;
    const float* __restrict__ pxa_row = PX + (size_t)(s0>0 ? s0-1 : 0)*NT1;
    const float* __restrict__ pxb_row = PX + (size_t)(hasB ? s0 : 0)*NT1;   // row s1-1 = s0
    const float* __restrict__ pya_row = PY + (size_t)s0*NT;
    const float* __restrict__ pyb_row = PY + (size_t)(hasB ? s1 : 0)*NT;
    float pA = NEGF, pB = NEGF;
    for(int d=0; d<=128; ++d){
      int c = d - i;
      if(c>=0 && c<=64){
        float aregs[8], bregs[8];
        #pragma unroll
        for(int j=0;j<8;j++){
          int t = 8*c+j;
          if(t<=512){
            float xa = (s0>0) ? __ldg(&pxa_row[t])   : 0.f;
            float ya = (t>0)  ? __ldg(&pya_row[t-1]) : 0.f;
            float vv = (s0>0) ? prevbuf[d&1][i-1][j] + xa : NEGF;
            float vh = (t>0)  ? pA + ya : NEGF;
            float a = (s0==0 && t==0) ? 0.f : lae2(vv,vh);
            pA = a; aregs[j] = a;
            if(hasB){
              float xb = __ldg(&pxb_row[t]);
              float yb = (t>0) ? __ldg(&pyb_row[t-1]) : 0.f;
              float bb = lae2(a + xb, (t>0) ? pB + yb : NEGF);
              pB = bb; bregs[j] = bb;
            }
          }
        }
        #pragma unroll
        for(int j=0;j<8;j++) prevbuf[(d+1)&1][i][j] = hasB ? bregs[j] : aregs[j];
        if(!which){
          if(c<64){
            *(float4*)&AL[(size_t)s0*NT1P + 8*c]   = make_float4(aregs[0],aregs[1],aregs[2],aregs[3]);
            *(float4*)&AL[(size_t)s0*NT1P + 8*c+4] = make_float4(aregs[4],aregs[5],aregs[6],aregs[7]);
            if(hasB){
              *(float4*)&AL[(size_t)s1*NT1P + 8*c]   = make_float4(bregs[0],bregs[1],bregs[2],bregs[3]);
              *(float4*)&AL[(size_t)s1*NT1P + 8*c+4] = make_float4(bregs[4],bregs[5],bregs[6],bregs[7]);
            }
          } else {
            AL[(size_t)s0*NT1P + 512] = aregs[0];
            if(hasB) AL[(size_t)s1*NT1P + 512] = bregs[0];
          }
        }
      }
      __syncthreads();
    }
    if(i==64) TOT[b] = pA;
  } else {
    int sA = NS - 2*i, sB = sA - 1;
    bool hasB = (sB >= 0);
    float* BE = g_beta + (size_t)b*NS1*NT1P;
    const float* __restrict__ pxa_row = PX + (size_t)(sA<NS ? sA : 0)*NT1;
    const float* __restrict__ pxb_row = PX + (size_t)(hasB ? sB : 0)*NT1;
    const float* __restrict__ pya_row = PY + (size_t)sA*NT;
    const float* __restrict__ pyb_row = PY + (size_t)(hasB ? sB : 0)*NT;
    float pA = NEGF, pB = NEGF;
    for(int d=0; d<=128; ++d){
      int c = 64 - (d - i);
      if(c>=0 && c<=64){
        float aregs[8], bregs[8];
        #pragma unroll
        for(int j=7;j>=0;j--){
          int t = 8*c+j;
          if(t<=512){
            float xa = (sA<NS) ? __ldg(&pxa_row[t]) : 0.f;
            float ya = (t<512) ? __ldg(&pya_row[t]) : 0.f;
            float vv = (sA<NS) ? prevbuf[d&1][i-1][j] + xa : NEGF;
            float vh = (t<512) ? pA + ya : NEGF;
            float a = (sA==NS && t==512) ? 0.f : lae2(vv,vh);
            pA = a; aregs[j] = a;
            if(hasB){
              float xb = __ldg(&pxb_row[t]);
              float yb = (t<512) ? __ldg(&pyb_row[t]) : 0.f;
              float bb = lae2(a + xb, (t<512) ? pB + yb : NEGF);
              pB = bb; bregs[j] = bb;
            }
          }
        }
        #pragma unroll
        for(int j=0;j<8;j++) prevbuf[(d+1)&1][i][j] = hasB ? bregs[j] : aregs[j];
        if(c<64){
          *(float4*)&BE[(size_t)sA*NT1P + 8*c]   = make_float4(aregs[0],aregs[1],aregs[2],aregs[3]);
          *(float4*)&BE[(size_t)sA*NT1P + 8*c+4] = make_float4(aregs[4],aregs[5],aregs[6],aregs[7]);
          if(hasB){
            *(float4*)&BE[(size_t)sB*NT1P + 8*c]   = make_float4(bregs[0],bregs[1],bregs[2],bregs[3]);
            *(float4*)&BE[(size_t)sB*NT1P + 8*c+4] = make_float4(bregs[4],bregs[5],bregs[6],bregs[7]);
          }
        } else {
          BE[(size_t)sA*NT1P + 512] = aregs[0];
          if(hasB) BE[(size_t)sB*NT1P + 512] = bregs[0];
        }
      }
      __syncthreads();
    }
  }
}

// ---------------- occupancy grads (merged) ----------------
__global__ void k_grads(){
  int idx = blockIdx.x*blockDim.x + threadIdx.x;
  const int N1 = NB*NS*NT1;
  if(idx < N1){
    int t = idx % NT1; int s = (idx/NT1) % NS; int b = idx/(NS*NT1);
    float a  = g_alpha[((size_t)b*NS1+s)*NT1P + t];
    float be = g_beta [((size_t)b*NS1+s+1)*NT1P + t];
    g_pxg[idx] = expf(a + g_px[idx] + be - g_total[b]);
  } else {
    int k = idx - N1;
    if(k >= NB*NS1*NT) return;
    int t = k % NT; int s = (k/NT) % NS1; int b = k/(NS1*NT);
    float a  = g_alpha[((size_t)b*NS1+s)*NT1P + t];
    float be = g_beta [((size_t)b*NS1+s)*NT1P + t + 1];
    g_pyg[k] = expf(a + g_py[k] + be - g_total[b]);
  }
}

// ---------------- pruning window argmax ----------------
__global__ void k_sbegin(){
  int idx = blockIdx.x*blockDim.x + threadIdx.x;
  if(idx >= NB*NT) return;
  int b = idx / NT, t = idx % NT;
  float U[NS1+1];
  U[0] = 0.f;
  for(int s=0;s<=NS;s++){
    float u = g_pyg[((size_t)b*NS1+s)*NT + t];
    if(s < NS) u += g_pxg[((size_t)b*NS+s)*NT1 + t];
    U[s+1] = U[s] + u;
  }
  float best = -3.4e38f; int arg = 0;
  for(int w=0; w<=NS1-RR; w++){
    float v = U[w+RR] - U[w];
    if(v > best){ best = v; arg = w; }
  }
  g_sb[idx] = arg;
}

__global__ void k_adjust(){
  int b = threadIdx.x;
  if(b >= NB) return;
  int m = 1<<30, ym = 1<<30;
  for(int t=NT-1; t>=0; --t){
    int v = g_sb[b*NT+t];
    m = min(m, v);
    int y = (RR-1)*t - m;
    ym = min(ym, y);
    int yc = max(ym, 0);
    g_sb[b*NT+t] = (RR-1)*t - yc;
  }
}

// ---------------- joiner band build (tanh.approx, bf16x2 stores) ------------
__global__ void k_buildA(const float* __restrict__ am, const float* __restrict__ lm){
  int b = blockIdx.x / NT, t = blockIdx.x % NT;
  __shared__ float amr[NC];
  for(int c=threadIdx.x;c<NC;c+=256) amr[c]=am[((size_t)b*NT+t)*NC+c];
  __syncthreads();
  int sb = g_sb[b*NT+t];
  size_t base = (size_t)(b*NT+t)*RR;
  int c = threadIdx.x*2;
  for(int j=0;j<RR;j++){
    const float* lr = lm + ((size_t)(b*NS1 + sb + j))*NC;
    float2 lv = *(const float2*)&lr[c];
    __nv_bfloat162 o;
    o.x = __float2bfloat16(tanh_ap(amr[c]   + lv.x));
    o.y = __float2bfloat16(tanh_ap(amr[c+1] + lv.y));
    *(__nv_bfloat162*)&g_A[(base+j)*NC + c] = o;
  }
}

// ---- joiner GEMM + fused band epilogue -------------------------------------
#define AP 40
#define BP 136
#define AST (128*AP)
#define BST (32*BP)
__global__ void __launch_bounds__(256) k_gemm(const int* __restrict__ tg,
                                              const float* __restrict__ bias){
  __shared__ __align__(16) char sbuf[(2*AST + 2*BST)*2];
  __nv_bfloat16* As = (__nv_bfloat16*)sbuf;
  __nv_bfloat16* Bs = (__nv_bfloat16*)(sbuf + 2*AST*2);
  int bn = blockIdx.x*128, bm = blockIdx.y*128;
  int tid = threadIdx.x, warp = tid>>5, lane = tid&31;
  int wm = warp & 1, wn = warp >> 1;
  uint32_t asb = (uint32_t)__cvta_generic_to_shared(As);
  uint32_t bsb = (uint32_t)__cvta_generic_to_shared(Bs);

  wmma::fragment<wmma::accumulator,16,16,16,float> acc[4][2];
  #pragma unroll
  for(int i=0;i<4;i++)
    #pragma unroll
    for(int j=0;j<2;j++) wmma::fill_fragment(acc[i][j], 0.f);

  auto loadst = [&](int ki, int st){
    #pragma unroll
    for(int it=0;it<2;it++){
      int v = tid + it*256, row = v>>2, q = v&3;
      cp16(asb + (st*AST + row*AP)*2 + q*16,
           &g_A[(size_t)(bm+row)*NC + ki*32 + q*8]);
    }
    #pragma unroll
    for(int it=0;it<2;it++){
      int v = tid + it*256, row = v>>4, q = v&15;
      cp16(bsb + (st*BST + row*BP)*2 + q*16,
           &g_W[(size_t)(ki*32+row)*NC + bn + q*8]);
    }
    asm volatile("cp.async.commit_group;");
  };

  loadst(0,0);
  for(int k=0;k<16;k++){
    int cur = k&1;
    if(k<15){
      loadst(k+1, cur^1);
      asm volatile("cp.async.wait_group 1;");
    } else {
      asm volatile("cp.async.wait_group 0;");
    }
    __syncthreads();
    __nv_bfloat16* Ac = As + cur*AST;
    __nv_bfloat16* Bc = Bs + cur*BST;
    #pragma unroll
    for(int kk=0;kk<2;kk++){
      wmma::fragment<wmma::matrix_a,16,16,16,__nv_bfloat16,wmma::row_major> a[4];
      wmma::fragment<wmma::matrix_b,16,16,16,__nv_bfloat16,wmma::row_major> bfr[2];
      #pragma unroll
      for(int i=0;i<4;i++) wmma::load_matrix_sync(a[i], &Ac[(wm*64+i*16)*AP + kk*16], AP);
      #pragma unroll
      for(int j=0;j<2;j++) wmma::load_matrix_sync(bfr[j], &Bc[(kk*16)*BP + wn*32 + j*16], BP);
      #pragma unroll
      for(int i=0;i<4;i++)
        #pragma unroll
        for(int j=0;j<2;j++) wmma::mma_sync(acc[i][j], a[i], bfr[j], acc[i][j]);
    }
    __syncthreads();
  }

  float* Sg = (float*)sbuf;
  #pragma unroll
  for(int ph=0; ph<2; ph++){
    if(wm == ph){
      #pragma unroll
      for(int i=0;i<4;i++)
        #pragma unroll
        for(int j=0;j<2;j++)
          wmma::store_matrix_sync(&Sg[(i*16)*132 + wn*32 + j*16], acc[i][j], 132,
                                  wmma::mem_row_major);
    }
    __syncthreads();
    #pragma unroll
    for(int q=0;q<8;q++){
      int r = warp*8 + q;
      float4 v4 = *(float4*)&Sg[r*132 + lane*4];
      float4 b4 = *(const float4*)&bias[bn + lane*4];
      float x0=v4.x+b4.x, x1=v4.y+b4.y, x2=v4.z+b4.z, x3=v4.w+b4.w;
      float mx = warpmax(fmaxf(fmaxf(x0,x1),fmaxf(x2,x3)));
      float ss = warpsum(expf(x0-mx)+expf(x1-mx)+expf(x2-mx)+expf(x3-mx));
      if(lane==0){
        int gr = bm + ph*64 + r;
        g_pmax[(size_t)gr*4 + blockIdx.x] = mx;
        g_psum[(size_t)gr*4 + blockIdx.x] = ss;
        int j = gr % RR; int bt = gr/RR; int b = bt/NT;
        int rng = g_sb[bt] + j;
        int sym = (rng < NS) ? tg[b*NS + rng] : 0;
        int sc = sym - bn;
        if(sc >= 0 && sc < 128) g_pxv[gr] = Sg[r*132 + sc] + bias[sym];
        if(bn == 0)             g_pyv[gr] = Sg[r*132]      + bias[0];
      }
    }
    __syncthreads();
  }
}

// ------- scatter band to full lattice, combining N-partial lse inline -------
__device__ __forceinline__ float band_lse(int gr){
  float4 m4 = *(const float4*)&g_pmax[(size_t)gr*4];
  float4 s4 = *(const float4*)&g_psum[(size_t)gr*4];
  float M = fmaxf(fmaxf(m4.x,m4.y), fmaxf(m4.z,m4.w));
  float S = s4.x*expf(m4.x-M) + s4.y*expf(m4.y-M) + s4.z*expf(m4.z-M) + s4.w*expf(m4.w-M);
  return M + logf(S);
}
__global__ void k_scatter(){
  int idx = blockIdx.x*blockDim.x + threadIdx.x;
  const int N1 = NB*NS*NT1;
  if(idx < N1){
    int t = idx % NT1; int s = (idx/NT1) % NS; int b = idx/(NS*NT1);
    float v = NEGF;
    if(t < NT){
      int sb = g_sb[b*NT+t]; int j = s - sb;
      if(j>=0 && j<RR){
        int gr = (b*NT+t)*RR + j;
        v = g_pxv[gr] - band_lse(gr);
      }
    }
    g_pxf[idx] = v;
  } else {
    int k = idx - N1;
    if(k >= NB*NS1*NT) return;
    int t = k % NT; int s = (k/NT) % NS1; int b = k/(NS1*NT);
    int sb = g_sb[b*NT+t]; int j = s - sb;
    float v = NEGF;
    if(j>=0 && j<RR){
      int gr = (b*NT+t)*RR + j;
      v = g_pyv[gr] - band_lse(gr);
    }
    g_pyf[k] = v;
  }
}

// ---------------- final loss ----------------
__global__ void k_final(float* out){
  float a=0.f, c=0.f;
  for(int b=0;b<NB;b++){ a += g_total[b]; c += g_total2[b]; }
  out[0] = -(0.1f*a + c)/(float)NB;
}

extern "C" void kernel_launch(void* const* d_in, const int* in_sizes, int n_in,
                              void* d_out, int out_size) {
  const float* am  = (const float*)d_in[0];
  const float* lm  = (const float*)d_in[1];
  const int*   tg  = (const int*)  d_in[2];
  const float* jw  = (const float*)d_in[4];
  const float* jb  = (const float*)d_in[5];
  float* out = (float*)d_out;
  (void)in_sizes; (void)n_in; (void)out_size;

  const int NPXY = NB*NS*NT1 + NB*NS1*NT;

  k_stats<<<(NB*NS1 + NB*NT + 7)/8, 256>>>(lm, am);     // 0
  k_norm<<<dim3(NT/64, 3, NB), 256>>>(am, lm, tg);      // 1
  k_convW<<<(NC*NC+255)/256, 256>>>(jw);                // 2
  k_dp<<<dim3(NB,2), 65>>>(0);                          // 3  <- profiled slot
  k_grads<<<(NPXY+255)/256, 256>>>();                   // 4
  k_sbegin<<<(NB*NT+255)/256, 256>>>();                 // 5
  k_adjust<<<1, NB>>>();                                // 6
  k_buildA<<<NB*NT, 256>>>(am, lm);                     // 7
  k_gemm<<<dim3(4, MROWS/128), 256>>>(tg, jb);          // 8
  k_scatter<<<(NPXY+255)/256, 256>>>();                 // 9
  k_dp<<<dim3(NB,1), 65>>>(1);                          // 10
  k_final<<<1,1>>>(out);                                // 11
}

// round 17
// speedup vs baseline: 1.4456x; 1.4456x over previous
#include <cuda_runtime.h>
#include <cuda_bf16.h>
#include <mma.h>
#include <math.h>
#include <cstdint>

using namespace nvcuda;

#define NB 8
#define NT 512
#define NS 128
#define NC 512
#define RR 19
#define NS1 129
#define NT1 513
#define NT1P 520
#define PXP 520
#define MROWS (NB*NT*RR)
#define NEGF (-1e20f)

// ---------------- device scratch (allocation-free module globals) -----------
__device__ float g_lm_max[NB*NS1];
__device__ float g_lm_lse[NB*NS1];
__device__ float g_lm_p[(size_t)NB*NS1*NC];
__device__ float g_am_max[NB*NT];
__device__ float g_am_p[(size_t)NB*NT*NC];
__device__ float g_px[(size_t)NB*NS*PXP];          // stride 520 (16B-aligned rows)
__device__ float g_py[(size_t)NB*NS1*NT + 8];      // +8 pad for chunk-64 loads
__device__ float g_alpha[(size_t)NB*NS1*NT1P];
__device__ float g_beta[(size_t)NB*NS1*NT1P];
__device__ float g_total[NB];
__device__ float g_total2[NB];
__device__ float g_pxg[(size_t)NB*NS*NT1];
__device__ float g_pyg[(size_t)NB*NS1*NT];
__device__ int   g_sb[NB*NT];
__device__ __nv_bfloat16 g_A[(size_t)MROWS*NC];
__device__ __nv_bfloat16 g_W[NC*NC];
__device__ float g_pmax[(size_t)MROWS*4];
__device__ float g_psum[(size_t)MROWS*4];
__device__ float g_pxv[MROWS];
__device__ float g_pyv[MROWS];
__device__ float g_pxf[(size_t)NB*NS*PXP];
__device__ float g_pyf[(size_t)NB*NS1*NT + 8];

// ---------------- helpers ----------------
__device__ __forceinline__ float warpmax(float v){
  #pragma unroll
  for(int o=16;o>0;o>>=1) v=fmaxf(v,__shfl_xor_sync(0xffffffffu,v,o));
  return v;
}
__device__ __forceinline__ float warpsum(float v){
  #pragma unroll
  for(int o=16;o>0;o>>=1) v+=__shfl_xor_sync(0xffffffffu,v,o);
  return v;
}
// fast logaddexp via MUFU ex2/lg2 (err ~1e-7 abs)
__device__ __forceinline__ float lae2(float a,float b){
  float mx=fmaxf(a,b), mn=fminf(a,b);
  float d = (mn-mx)*1.4426950408889634f;
  float e; asm("ex2.approx.f32 %0, %1;" : "=f"(e) : "f"(d));
  float l; asm("lg2.approx.f32 %0, %1;" : "=f"(l) : "f"(1.0f+e));
  return mx + l*0.6931471805599453f;
}
__device__ __forceinline__ float tanh_ap(float x){
  float r; asm("tanh.approx.f32 %0, %1;" : "=f"(r) : "f"(x)); return r;
}
__device__ __forceinline__ void cp16(uint32_t dst, const void* src){
  asm volatile("cp.async.cg.shared.global [%0], [%1], 16;" :: "r"(dst), "l"(src));
}
#define C4(v,j) ((j)==0?(v).x:((j)==1?(v).y:((j)==2?(v).z:(v).w)))

// ---------------- merged row stats (lm rows then am rows) -------------------
__global__ void k_stats(const float* __restrict__ lm, const float* __restrict__ am){
  int row = blockIdx.x*8 + (threadIdx.x>>5);
  int lane = threadIdx.x & 31;
  if(row < NB*NS1){
    const float* L = lm + (size_t)row*NC;
    float v[16]; float mx = -3.4e38f;
    #pragma unroll
    for(int j=0;j<16;j++){ v[j]=L[lane+32*j]; mx=fmaxf(mx,v[j]); }
    mx = warpmax(mx);
    float s = 0.f;
    #pragma unroll
    for(int j=0;j<16;j++){ float e=expf(v[j]-mx); s+=e; g_lm_p[(size_t)row*NC+lane+32*j]=e; }
    s = warpsum(s);
    if(lane==0){ g_lm_max[row]=mx; g_lm_lse[row]=mx+logf(s); }
  } else {
    int r = row - NB*NS1;
    if(r >= NB*NT) return;
    const float* A = am + (size_t)r*NC;
    float v[16]; float mx = -3.4e38f;
    #pragma unroll
    for(int j=0;j<16;j++){ v[j]=A[lane+32*j]; mx=fmaxf(mx,v[j]); }
    mx = warpmax(mx);
    #pragma unroll
    for(int j=0;j<16;j++) g_am_p[(size_t)r*NC + lane+32*j] = expf(v[j]-mx);
    if(lane==0) g_am_max[r]=mx;
  }
}

// ---- normalizers (64x64 tile, 4x4 reg blocking) + fused px/py epilogue -----
__global__ void __launch_bounds__(256) k_norm(const float* __restrict__ am,
                                              const float* __restrict__ lm,
                                              const int* __restrict__ tg){
  int b = blockIdx.z, s0 = blockIdx.y*64, t0 = blockIdx.x*64;
  __shared__ float Ls[64][17], Am[64][17];
  int tid = threadIdx.x;
  int ty = tid>>4, tx = tid&15;
  float acc[4][4];
  #pragma unroll
  for(int i=0;i<4;i++)
    #pragma unroll
    for(int j=0;j<4;j++) acc[i][j]=0.f;

  int lr = tid>>2, lq = (tid&3)*4;
  for(int c0=0;c0<NC;c0+=16){
    {
      int s = s0 + lr;
      float4 v = (s<NS1) ? *(const float4*)&g_lm_p[((size_t)b*NS1+s)*NC + c0 + lq]
                         : make_float4(0.f,0.f,0.f,0.f);
      Ls[lr][lq]=v.x; Ls[lr][lq+1]=v.y; Ls[lr][lq+2]=v.z; Ls[lr][lq+3]=v.w;
    }
    {
      float4 v = *(const float4*)&g_am_p[((size_t)b*NT + t0 + lr)*NC + c0 + lq];
      Am[lr][lq]=v.x; Am[lr][lq+1]=v.y; Am[lr][lq+2]=v.z; Am[lr][lq+3]=v.w;
    }
    __syncthreads();
    #pragma unroll
    for(int c=0;c<16;c++){
      float a0=Ls[ty*4+0][c], a1=Ls[ty*4+1][c], a2=Ls[ty*4+2][c], a3=Ls[ty*4+3][c];
      float e0=Am[tx*4+0][c], e1=Am[tx*4+1][c], e2=Am[tx*4+2][c], e3=Am[tx*4+3][c];
      acc[0][0]+=a0*e0; acc[0][1]+=a0*e1; acc[0][2]+=a0*e2; acc[0][3]+=a0*e3;
      acc[1][0]+=a1*e0; acc[1][1]+=a1*e1; acc[1][2]+=a1*e2; acc[1][3]+=a1*e3;
      acc[2][0]+=a2*e0; acc[2][1]+=a2*e1; acc[2][2]+=a2*e2; acc[2][3]+=a2*e3;
      acc[3][0]+=a3*e0; acc[3][1]+=a3*e1; acc[3][2]+=a3*e2; acc[3][3]+=a3*e3;
    }
    __syncthreads();
  }
  #pragma unroll
  for(int i=0;i<4;i++){
    int s = s0 + ty*4 + i;
    if(s >= NS1) continue;
    float lmx = g_lm_max[b*NS1+s];
    float lse = g_lm_lse[b*NS1+s];
    float lm0 = lm[((size_t)b*NS1+s)*NC];
    int sym = (s<NS) ? tg[b*NS+s] : 0;
    float lms = (s<NS) ? lm[((size_t)b*NS1+s)*NC + sym] : 0.f;
    #pragma unroll
    for(int j=0;j<4;j++){
      int t = t0 + tx*4 + j;
      float nrm = logf(acc[i][j]) + lmx + g_am_max[b*NT+t];
      float am0 = am[((size_t)b*NT+t)*NC];
      g_py[((size_t)b*NS1+s)*NT+t] = 0.75f*(am0+lm0-nrm) + 0.25f*(lm0-lse);
      if(s<NS){
        float ams = am[((size_t)b*NT+t)*NC + sym];
        g_px[((size_t)b*NS+s)*PXP+t] = 0.75f*(ams+lms-nrm) + 0.25f*(lms-lse);
      }
    }
  }
}

// ---------------- W conversion + px t=NT sentinel init ----------------------
__global__ void k_convW(const float* __restrict__ w){
  int idx = blockIdx.x*blockDim.x + threadIdx.x;
  if(idx < NC*NC) g_W[idx] = __float2bfloat16(w[idx]);
  if(idx < NB*NS) g_px[(size_t)idx*PXP + NT] = NEGF;
}

// ------ lattice DP: single-warp wavefront, shuffles, no barriers ------------
// forward: lane l owns rows 4l..4l+3 (+row 128 for lane 31); chunk c=d-l covers t=8c..8c+7
// backward: lane l owns rows 128-4l..125-4l (+row 0 for lane 31); chunk c=64-(d-l), cols descending
__global__ void __launch_bounds__(32) k_dp(int which){
  int b = blockIdx.x;
  int l = threadIdx.x;
  const unsigned FULL = 0xffffffffu;
  float out0[8],out1[8],out2[8],out3[8],out4[8];
  float bot[8];
  #pragma unroll
  for(int j=0;j<8;j++){ out0[j]=out1[j]=out2[j]=out3[j]=out4[j]=NEGF; bot[j]=NEGF; }
  bool ex = (l==31);

  if(blockIdx.y==0){
    const float* PX = (which ? g_pxf : g_px) + (size_t)b*NS*PXP;
    const float* PY = (which ? g_pyf : g_py) + (size_t)b*NS1*NT;
    float* AL = g_alpha + (size_t)b*NS1*NT1P;
    int s0 = 4*l;
    const float* __restrict__ px0 = PX + (size_t)(l ? (s0-1) : 0)*PXP;
    const float* __restrict__ px1 = PX + (size_t)s0*PXP;
    const float* __restrict__ px2 = PX + (size_t)(s0+1)*PXP;
    const float* __restrict__ px3 = PX + (size_t)(s0+2)*PXP;
    const float* __restrict__ px4 = PX + (size_t)127*PXP;
    const float* __restrict__ py0 = PY + (size_t)s0*NT;
    const float* __restrict__ py1 = PY + (size_t)(s0+1)*NT;
    const float* __restrict__ py2 = PY + (size_t)(s0+2)*NT;
    const float* __restrict__ py3 = PY + (size_t)(s0+3)*NT;
    const float* __restrict__ py4 = PY + (size_t)128*NT;
    float c0=NEGF,c1=NEGF,c2=NEGF,c3=NEGF,c4=NEGF;
    float yp0=0.f,yp1=0.f,yp2=0.f,yp3=0.f,yp4=0.f;
    for(int d=0; d<96; ++d){
      float top[8];
      #pragma unroll
      for(int j=0;j<8;j++) top[j] = __shfl_up_sync(FULL, bot[j], 1);
      int c = d - l;
      if(c>=0 && c<=64){
        int o = 8*c;
        float4 xa0=*(const float4*)&px0[o], xb0=*(const float4*)&px0[o+4];
        float4 xa1=*(const float4*)&px1[o], xb1=*(const float4*)&px1[o+4];
        float4 xa2=*(const float4*)&px2[o], xb2=*(const float4*)&px2[o+4];
        float4 xa3=*(const float4*)&px3[o], xb3=*(const float4*)&px3[o+4];
        float4 ya0=*(const float4*)&py0[o], yb0=*(const float4*)&py0[o+4];
        float4 ya1=*(const float4*)&py1[o], yb1=*(const float4*)&py1[o+4];
        float4 ya2=*(const float4*)&py2[o], yb2=*(const float4*)&py2[o+4];
        float4 ya3=*(const float4*)&py3[o], yb3=*(const float4*)&py3[o+4];
        float4 xa4,xb4,ya4,yb4;
        if(ex){ xa4=*(const float4*)&px4[o]; xb4=*(const float4*)&px4[o+4];
                ya4=*(const float4*)&py4[o]; yb4=*(const float4*)&py4[o+4]; }
        #pragma unroll
        for(int j=0;j<8;j++){
          int t = o + j;
          if(t<=NT){
            float X0 = (j<4)?C4(xa0,j):C4(xb0,j-4);
            float Y0 = (j==0)?yp0:((j<5)?C4(ya0,j-1):C4(yb0,j-5));
            float vv = (l>0) ? top[j]+X0 : NEGF;
            float vh = (t>0) ? c0+Y0 : NEGF;
            float a0 = lae2(vv,vh);
            if(l==0 && t==0) a0 = 0.f;
            c0=a0; out0[j]=a0;
            float X1 = (j<4)?C4(xa1,j):C4(xb1,j-4);
            float Y1 = (j==0)?yp1:((j<5)?C4(ya1,j-1):C4(yb1,j-5));
            float a1 = lae2(a0+X1, (t>0)?c1+Y1:NEGF); c1=a1; out1[j]=a1;
            float X2 = (j<4)?C4(xa2,j):C4(xb2,j-4);
            float Y2 = (j==0)?yp2:((j<5)?C4(ya2,j-1):C4(yb2,j-5));
            float a2 = lae2(a1+X2, (t>0)?c2+Y2:NEGF); c2=a2; out2[j]=a2;
            float X3 = (j<4)?C4(xa3,j):C4(xb3,j-4);
            float Y3 = (j==0)?yp3:((j<5)?C4(ya3,j-1):C4(yb3,j-5));
            float a3 = lae2(a2+X3, (t>0)?c3+Y3:NEGF); c3=a3; out3[j]=a3;
            if(ex){
              float X4 = (j<4)?C4(xa4,j):C4(xb4,j-4);
              float Y4 = (j==0)?yp4:((j<5)?C4(ya4,j-1):C4(yb4,j-5));
              float a4 = lae2(a3+X4, (t>0)?c4+Y4:NEGF); c4=a4; out4[j]=a4;
            }
          }
        }
        yp0=yb0.w; yp1=yb1.w; yp2=yb2.w; yp3=yb3.w; if(ex) yp4=yb4.w;
        #pragma unroll
        for(int j=0;j<8;j++) bot[j]=out3[j];
        if(!which){
          float* A0 = &AL[(size_t)s0*NT1P + o];
          *(float4*)A0     = make_float4(out0[0],out0[1],out0[2],out0[3]);
          *(float4*)(A0+4) = make_float4(out0[4],out0[5],out0[6],out0[7]);
          float* A1 = &AL[(size_t)(s0+1)*NT1P + o];
          *(float4*)A1     = make_float4(out1[0],out1[1],out1[2],out1[3]);
          *(float4*)(A1+4) = make_float4(out1[4],out1[5],out1[6],out1[7]);
          float* A2 = &AL[(size_t)(s0+2)*NT1P + o];
          *(float4*)A2     = make_float4(out2[0],out2[1],out2[2],out2[3]);
          *(float4*)(A2+4) = make_float4(out2[4],out2[5],out2[6],out2[7]);
          float* A3 = &AL[(size_t)(s0+3)*NT1P + o];
          *(float4*)A3     = make_float4(out3[0],out3[1],out3[2],out3[3]);
          *(float4*)(A3+4) = make_float4(out3[4],out3[5],out3[6],out3[7]);
          if(ex){
            float* A4 = &AL[(size_t)128*NT1P + o];
            *(float4*)A4     = make_float4(out4[0],out4[1],out4[2],out4[3]);
            *(float4*)(A4+4) = make_float4(out4[4],out4[5],out4[6],out4[7]);
          }
        }
      }
    }
    if(ex){ if(which) g_total2[b]=c4; else g_total[b]=c4; }
  } else {
    const float* PX = g_px + (size_t)b*NS*PXP;
    const float* PY = g_py + (size_t)b*NS1*NT;
    float* BE = g_beta + (size_t)b*NS1*NT1P;
    int sA = 128 - 4*l;
    const float* __restrict__ px0 = PX + (size_t)(l ? sA : 0)*PXP;
    const float* __restrict__ px1 = PX + (size_t)(sA-1)*PXP;
    const float* __restrict__ px2 = PX + (size_t)(sA-2)*PXP;
    const float* __restrict__ px3 = PX + (size_t)(sA-3)*PXP;
    const float* __restrict__ px4 = PX;
    const float* __restrict__ py0 = PY + (size_t)sA*NT;
    const float* __restrict__ py1 = PY + (size_t)(sA-1)*NT;
    const float* __restrict__ py2 = PY + (size_t)(sA-2)*NT;
    const float* __restrict__ py3 = PY + (size_t)(sA-3)*NT;
    const float* __restrict__ py4 = PY;
    float c0=NEGF,c1=NEGF,c2=NEGF,c3=NEGF,c4=NEGF;
    for(int d=0; d<96; ++d){
      float top[8];
      #pragma unroll
      for(int j=0;j<8;j++) top[j] = __shfl_up_sync(FULL, bot[j], 1);
      int c = 64 - (d - l);
      if(c>=0 && c<=64 && d>=l){
        int o = 8*c;
        float4 xa0=*(const float4*)&px0[o], xb0=*(const float4*)&px0[o+4];
        float4 xa1=*(const float4*)&px1[o], xb1=*(const float4*)&px1[o+4];
        float4 xa2=*(const float4*)&px2[o], xb2=*(const float4*)&px2[o+4];
        float4 xa3=*(const float4*)&px3[o], xb3=*(const float4*)&px3[o+4];
        float4 ya0=*(const float4*)&py0[o], yb0=*(const float4*)&py0[o+4];
        float4 ya1=*(const float4*)&py1[o], yb1=*(const float4*)&py1[o+4];
        float4 ya2=*(const float4*)&py2[o], yb2=*(const float4*)&py2[o+4];
        float4 ya3=*(const float4*)&py3[o], yb3=*(const float4*)&py3[o+4];
        float4 xa4,xb4,ya4,yb4;
        if(ex){ xa4=*(const float4*)&px4[o]; xb4=*(const float4*)&px4[o+4];
                ya4=*(const float4*)&py4[o]; yb4=*(const float4*)&py4[o+4]; }
        #pragma unroll
        for(int j=7;j>=0;j--){
          int t = o + j;
          if(t<=NT){
            float X0 = (j<4)?C4(xa0,j):C4(xb0,j-4);
            float Y0 = (j<4)?C4(ya0,j):C4(yb0,j-4);
            float vv = (l>0) ? top[j]+X0 : NEGF;
            float vh = (t<NT) ? c0+Y0 : NEGF;
            float a0 = lae2(vv,vh);
            if(l==0 && t==NT) a0 = 0.f;
            c0=a0; out0[j]=a0;
            float X1 = (j<4)?C4(xa1,j):C4(xb1,j-4);
            float Y1 = (j<4)?C4(ya1,j):C4(yb1,j-4);
            float a1 = lae2(a0+X1, (t<NT)?c1+Y1:NEGF); c1=a1; out1[j]=a1;
            float X2 = (j<4)?C4(xa2,j):C4(xb2,j-4);
            float Y2 = (j<4)?C4(ya2,j):C4(yb2,j-4);
            float a2 = lae2(a1+X2, (t<NT)?c2+Y2:NEGF); c2=a2; out2[j]=a2;
            float X3 = (j<4)?C4(xa3,j):C4(xb3,j-4);
            float Y3 = (j<4)?C4(ya3,j):C4(yb3,j-4);
            float a3 = lae2(a2+X3, (t<NT)?c3+Y3:NEGF); c3=a3; out3[j]=a3;
            if(ex){
              float X4 = (j<4)?C4(xa4,j):C4(xb4,j-4);
              float Y4 = (j<4)?C4(ya4,j):C4(yb4,j-4);
              float a4 = lae2(a3+X4, (t<NT)?c4+Y4:NEGF); c4=a4; out4[j]=a4;
            }
          }
        }
        #pragma unroll
        for(int j=0;j<8;j++) bot[j]=out3[j];
        float* B0 = &BE[(size_t)sA*NT1P + o];
        *(float4*)B0     = make_float4(out0[0],out0[1],out0[2],out0[3]);
        *(float4*)(B0+4) = make_float4(out0[4],out0[5],out0[6],out0[7]);
        float* B1 = &BE[(size_t)(sA-1)*NT1P + o];
        *(float4*)B1     = make_float4(out1[0],out1[1],out1[2],out1[3]);
        *(float4*)(B1+4) = make_float4(out1[4],out1[5],out1[6],out1[7]);
        float* B2 = &BE[(size_t)(sA-2)*NT1P + o];
        *(float4*)B2     = make_float4(out2[0],out2[1],out2[2],out2[3]);
        *(float4*)(B2+4) = make_float4(out2[4],out2[5],out2[6],out2[7]);
        float* B3 = &BE[(size_t)(sA-3)*NT1P + o];
        *(float4*)B3     = make_float4(out3[0],out3[1],out3[2],out3[3]);
        *(float4*)(B3+4) = make_float4(out3[4],out3[5],out3[6],out3[7]);
        if(ex){
          float* B4 = &BE[o];
          *(float4*)B4     = make_float4(out4[0],out4[1],out4[2],out4[3]);
          *(float4*)(B4+4) = make_float4(out4[4],out4[5],out4[6],out4[7]);
        }
      }
    }
  }
}

// ---------------- occupancy grads (merged) ----------------
__global__ void k_grads(){
  int idx = blockIdx.x*blockDim.x + threadIdx.x;
  const int N1 = NB*NS*NT1;
  if(idx < N1){
    int t = idx % NT1; int s = (idx/NT1) % NS; int b = idx/(NS*NT1);
    float a  = g_alpha[((size_t)b*NS1+s)*NT1P + t];
    float be = g_beta [((size_t)b*NS1+s+1)*NT1P + t];
    g_pxg[idx] = expf(a + g_px[((size_t)b*NS+s)*PXP + t] + be - g_total[b]);
  } else {
    int k = idx - N1;
    if(k >= NB*NS1*NT) return;
    int t = k % NT; int s = (k/NT) % NS1; int b = k/(NS1*NT);
    float a  = g_alpha[((size_t)b*NS1+s)*NT1P + t];
    float be = g_beta [((size_t)b*NS1+s)*NT1P + t + 1];
    g_pyg[k] = expf(a + g_py[k] + be - g_total[b]);
  }
}

// ---------------- pruning window argmax ----------------
__global__ void k_sbegin(){
  int idx = blockIdx.x*blockDim.x + threadIdx.x;
  if(idx >= NB*NT) return;
  int b = idx / NT, t = idx % NT;
  float U[NS1+1];
  U[0] = 0.f;
  for(int s=0;s<=NS;s++){
    float u = g_pyg[((size_t)b*NS1+s)*NT + t];
    if(s < NS) u += g_pxg[((size_t)b*NS+s)*NT1 + t];
    U[s+1] = U[s] + u;
  }
  float best = -3.4e38f; int arg = 0;
  for(int w=0; w<=NS1-RR; w++){
    float v = U[w+RR] - U[w];
    if(v > best){ best = v; arg = w; }
  }
  g_sb[idx] = arg;
}

__global__ void k_adjust(){
  int b = threadIdx.x;
  if(b >= NB) return;
  int m = 1<<30, ym = 1<<30;
  for(int t=NT-1; t>=0; --t){
    int v = g_sb[b*NT+t];
    m = min(m, v);
    int y = (RR-1)*t - m;
    ym = min(ym, y);
    int yc = max(ym, 0);
    g_sb[b*NT+t] = (RR-1)*t - yc;
  }
}

// ---------------- joiner band build (tanh.approx, bf16x2 stores) ------------
__global__ void k_buildA(const float* __restrict__ am, const float* __restrict__ lm){
  int b = blockIdx.x / NT, t = blockIdx.x % NT;
  __shared__ float amr[NC];
  for(int c=threadIdx.x;c<NC;c+=256) amr[c]=am[((size_t)b*NT+t)*NC+c];
  __syncthreads();
  int sb = g_sb[b*NT+t];
  size_t base = (size_t)(b*NT+t)*RR;
  int c = threadIdx.x*2;
  for(int j=0;j<RR;j++){
    const float* lr = lm + ((size_t)(b*NS1 + sb + j))*NC;
    float2 lv = *(const float2*)&lr[c];
    __nv_bfloat162 o;
    o.x = __float2bfloat16(tanh_ap(amr[c]   + lv.x));
    o.y = __float2bfloat16(tanh_ap(amr[c+1] + lv.y));
    *(__nv_bfloat162*)&g_A[(base+j)*NC + c] = o;
  }
}

// ---- joiner GEMM + fused band epilogue -------------------------------------
#define AP 40
#define BP 136
#define AST (128*AP)
#define BST (32*BP)
__global__ void __launch_bounds__(256) k_gemm(const int* __restrict__ tg,
                                              const float* __restrict__ bias){
  __shared__ __align__(16) char sbuf[(2*AST + 2*BST)*2];
  __nv_bfloat16* As = (__nv_bfloat16*)sbuf;
  __nv_bfloat16* Bs = (__nv_bfloat16*)(sbuf + 2*AST*2);
  int bn = blockIdx.x*128, bm = blockIdx.y*128;
  int tid = threadIdx.x, warp = tid>>5, lane = tid&31;
  int wm = warp & 1, wn = warp >> 1;
  uint32_t asb = (uint32_t)__cvta_generic_to_shared(As);
  uint32_t bsb = (uint32_t)__cvta_generic_to_shared(Bs);

  wmma::fragment<wmma::accumulator,16,16,16,float> acc[4][2];
  #pragma unroll
  for(int i=0;i<4;i++)
    #pragma unroll
    for(int j=0;j<2;j++) wmma::fill_fragment(acc[i][j], 0.f);

  auto loadst = [&](int ki, int st){
    #pragma unroll
    for(int it=0;it<2;it++){
      int v = tid + it*256, row = v>>2, q = v&3;
      cp16(asb + (st*AST + row*AP)*2 + q*16,
           &g_A[(size_t)(bm+row)*NC + ki*32 + q*8]);
    }
    #pragma unroll
    for(int it=0;it<2;it++){
      int v = tid + it*256, row = v>>4, q = v&15;
      cp16(bsb + (st*BST + row*BP)*2 + q*16,
           &g_W[(size_t)(ki*32+row)*NC + bn + q*8]);
    }
    asm volatile("cp.async.commit_group;");
  };

  loadst(0,0);
  for(int k=0;k<16;k++){
    int cur = k&1;
    if(k<15){
      loadst(k+1, cur^1);
      asm volatile("cp.async.wait_group 1;");
    } else {
      asm volatile("cp.async.wait_group 0;");
    }
    __syncthreads();
    __nv_bfloat16* Ac = As + cur*AST;
    __nv_bfloat16* Bc = Bs + cur*BST;
    #pragma unroll
    for(int kk=0;kk<2;kk++){
      wmma::fragment<wmma::matrix_a,16,16,16,__nv_bfloat16,wmma::row_major> a[4];
      wmma::fragment<wmma::matrix_b,16,16,16,__nv_bfloat16,wmma::row_major> bfr[2];
      #pragma unroll
      for(int i=0;i<4;i++) wmma::load_matrix_sync(a[i], &Ac[(wm*64+i*16)*AP + kk*16], AP);
      #pragma unroll
      for(int j=0;j<2;j++) wmma::load_matrix_sync(bfr[j], &Bc[(kk*16)*BP + wn*32 + j*16], BP);
      #pragma unroll
      for(int i=0;i<4;i++)
        #pragma unroll
        for(int j=0;j<2;j++) wmma::mma_sync(acc[i][j], a[i], bfr[j], acc[i][j]);
    }
    __syncthreads();
  }

  float* Sg = (float*)sbuf;
  #pragma unroll
  for(int ph=0; ph<2; ph++){
    if(wm == ph){
      #pragma unroll
      for(int i=0;i<4;i++)
        #pragma unroll
        for(int j=0;j<2;j++)
          wmma::store_matrix_sync(&Sg[(i*16)*132 + wn*32 + j*16], acc[i][j], 132,
                                  wmma::mem_row_major);
    }
    __syncthreads();
    #pragma unroll
    for(int q=0;q<8;q++){
      int r = warp*8 + q;
      float4 v4 = *(float4*)&Sg[r*132 + lane*4];
      float4 b4 = *(const float4*)&bias[bn + lane*4];
      float x0=v4.x+b4.x, x1=v4.y+b4.y, x2=v4.z+b4.z, x3=v4.w+b4.w;
      float mx = warpmax(fmaxf(fmaxf(x0,x1),fmaxf(x2,x3)));
      float ss = warpsum(expf(x0-mx)+expf(x1-mx)+expf(x2-mx)+expf(x3-mx));
      if(lane==0){
        int gr = bm + ph*64 + r;
        g_pmax[(size_t)gr*4 + blockIdx.x] = mx;
        g_psum[(size_t)gr*4 + blockIdx.x] = ss;
        int j = gr % RR; int bt = gr/RR; int b = bt/NT;
        int rng = g_sb[bt] + j;
        int sym = (rng < NS) ? tg[b*NS + rng] : 0;
        int sc = sym - bn;
        if(sc >= 0 && sc < 128) g_pxv[gr] = Sg[r*132 + sc] + bias[sym];
        if(bn == 0)             g_pyv[gr] = Sg[r*132]      + bias[0];
      }
    }
    __syncthreads();
  }
}

// ------- scatter band to full lattice, combining N-partial lse inline -------
__device__ __forceinline__ float band_lse(int gr){
  float4 m4 = *(const float4*)&g_pmax[(size_t)gr*4];
  float4 s4 = *(const float4*)&g_psum[(size_t)gr*4];
  float M = fmaxf(fmaxf(m4.x,m4.y), fmaxf(m4.z,m4.w));
  float S = s4.x*expf(m4.x-M) + s4.y*expf(m4.y-M) + s4.z*expf(m4.z-M) + s4.w*expf(m4.w-M);
  return M + logf(S);
}
__global__ void k_scatter(){
  int idx = blockIdx.x*blockDim.x + threadIdx.x;
  const int N1 = NB*NS*NT1;
  if(idx < N1){
    int t = idx % NT1; int s = (idx/NT1) % NS; int b = idx/(NS*NT1);
    float v = NEGF;
    if(t < NT){
      int sb = g_sb[b*NT+t]; int j = s - sb;
      if(j>=0 && j<RR){
        int gr = (b*NT+t)*RR + j;
        v = g_pxv[gr] - band_lse(gr);
      }
    }
    g_pxf[((size_t)b*NS+s)*PXP + t] = v;
  } else {
    int k = idx - N1;
    if(k >= NB*NS1*NT) return;
    int t = k % NT; int s = (k/NT) % NS1; int b = k/(NS1*NT);
    int sb = g_sb[b*NT+t]; int j = s - sb;
    float v = NEGF;
    if(j>=0 && j<RR){
      int gr = (b*NT+t)*RR + j;
      v = g_pyv[gr] - band_lse(gr);
    }
    g_pyf[k] = v;
  }
}

// ---------------- final loss ----------------
__global__ void k_final(float* out){
  float a=0.f, c=0.f;
  for(int b=0;b<NB;b++){ a += g_total[b]; c += g_total2[b]; }
  out[0] = -(0.1f*a + c)/(float)NB;
}

extern "C" void kernel_launch(void* const* d_in, const int* in_sizes, int n_in,
                              void* d_out, int out_size) {
  const float* am  = (const float*)d_in[0];
  const float* lm  = (const float*)d_in[1];
  const int*   tg  = (const int*)  d_in[2];
  const float* jw  = (const float*)d_in[4];
  const float* jb  = (const float*)d_in[5];
  float* out = (float*)d_out;
  (void)in_sizes; (void)n_in; (void)out_size;

  const int NPXY = NB*NS*NT1 + NB*NS1*NT;

  k_stats<<<(NB*NS1 + NB*NT + 7)/8, 256>>>(lm, am);     // 0
  k_norm<<<dim3(NT/64, 3, NB), 256>>>(am, lm, tg);      // 1
  k_convW<<<(NC*NC+255)/256, 256>>>(jw);                // 2
  k_dp<<<dim3(NB,2), 32>>>(0);                          // 3  <- profiled slot
  k_grads<<<(NPXY+255)/256, 256>>>();                   // 4
  k_sbegin<<<(NB*NT+255)/256, 256>>>();                 // 5
  k_adjust<<<1, NB>>>();                                // 6
  k_buildA<<<NB*NT, 256>>>(am, lm);                     // 7
  k_gemm<<<dim3(4, MROWS/128), 256>>>(tg, jb);          // 8
  k_scatter<<<(NPXY+255)/256, 256>>>();                 // 9
  k_dp<<<dim3(NB,1), 32>>>(1);                          // 10
  k_final<<<1,1>>>(out);                                // 11
}